// round 9
// baseline (speedup 1.0000x reference)
#include <cuda_runtime.h>
#include <cuda_fp16.h>
#include <cstdint>

#define NQ  2048
#define DH  64
#define WIN 512
#define QT  128
// 0.125 * log2(e) folded into Q; softmax in log2 domain via ex2.approx
#define QS2 0.18033688011112042f

// byte offsets in dynamic smem (total 66560 B -> 3 CTAs/SM)
#define SMB_QH  0        // 128 rows x 32 u32 (fp16x2), word ^ ((row&7)<<2)
#define SMB_KH  16384    // 64 keys x 32 u32 (fp16x2), same swizzle
#define SMB_VT  24576    // Vt fp16 [d][keypair], stride 36 u32, kp ^ ((d>>4)&3)
#define SMB_KS  33792    // K f32 staging 64x64, chunk ^ (key&7)
#define SMB_VS  50176    // V f32 staging 64x64, plain
#define SMB_TOT 66560

static __device__ __forceinline__ float ex2f(float x) {
    float y; asm("ex2.approx.f32 %0, %1;" : "=f"(y) : "f"(x)); return y;
}
static __device__ __forceinline__ uint32_t packh2(float lo, float hi) {
    __half2 h = __floats2half2_rn(lo, hi);
    return *(uint32_t*)&h;
}
static __device__ __forceinline__ void mma_f16(float* d, const uint32_t* a,
                                               uint32_t b0, uint32_t b1) {
    asm volatile(
        "mma.sync.aligned.m16n8k16.row.col.f32.f16.f16.f32 "
        "{%0,%1,%2,%3}, {%4,%5,%6,%7}, {%8,%9}, {%0,%1,%2,%3};"
        : "+f"(d[0]), "+f"(d[1]), "+f"(d[2]), "+f"(d[3])
        : "r"(a[0]), "r"(a[1]), "r"(a[2]), "r"(a[3]), "r"(b0), "r"(b1));
}
static __device__ __forceinline__ void ldsm_x4(uint32_t* r, uint32_t addr) {
    asm volatile("ldmatrix.sync.aligned.m8n8.x4.shared.b16 {%0,%1,%2,%3}, [%4];"
                 : "=r"(r[0]), "=r"(r[1]), "=r"(r[2]), "=r"(r[3]) : "r"(addr));
}
static __device__ __forceinline__ uint32_t smem_u32(const void* p) {
    uint32_t a;
    asm("{ .reg .u64 t; cvta.to.shared.u64 t, %1; cvt.u32.u64 %0, t; }" : "=r"(a) : "l"(p));
    return a;
}
static __device__ __forceinline__ void cpa16(uint32_t dst, const float* src) {
    asm volatile("cp.async.cg.shared.global [%0], [%1], 16;" :: "r"(dst), "l"(src));
}

__global__ __launch_bounds__(128, 3)
void swa_mma_kernel(const float* __restrict__ q, const float* __restrict__ k,
                    const float* __restrict__ v, float* __restrict__ out)
{
    extern __shared__ char smc[];
    const uint32_t sb = smem_u32(smc);
    uint32_t* Qh = (uint32_t*)(smc + SMB_QH);
    uint32_t* Kh = (uint32_t*)(smc + SMB_KH);
    uint32_t* Vt = (uint32_t*)(smc + SMB_VT);
    float*    Ks = (float*)(smc + SMB_KS);
    float*    Vs = (float*)(smc + SMB_VS);

    const int tid  = threadIdx.x;
    const int w    = tid >> 5;
    const int lane = tid & 31;
    const int gid  = lane >> 2;
    const int tig  = lane & 3;

    const int qt2 = (int)gridDim.x - 1 - (int)blockIdx.x;   // long CTAs first
    const int bh  = blockIdx.y;
    const int qs  = qt2 * QT;

    const float* qp = q + (size_t)bh * NQ * DH;
    const float* kp = k + (size_t)bh * NQ * DH;
    const float* vp = v + (size_t)bh * NQ * DH;

    const int kt_lo = (2 * qt2 - 8) > 0 ? (2 * qt2 - 8) : 0;
    const int kt_hi = 2 * qt2 + 1;

    // ---- ldmatrix per-lane address components ----
    const int k_row = 8 * ((lane >> 4) & 1) + (lane & 7);     // key within 16-key block
    const int k_b1  = ((lane >> 3) & 1) << 2;                 // b0/b1 group
    const int l_s   = (lane & 7) << 2;                        // XOR swizzle term
    const int q_row = (lane & 7) + 8 * ((lane >> 3) & 1);     // row within m16 tile
    const int q_b1  = ((lane >> 4) & 1) << 2;

    // ---- prefetch first K/V tile into staging ----
    {
        const float* kg = kp + (size_t)kt_lo * 64 * DH;
        const float* vg = vp + (size_t)kt_lo * 64 * DH;
#pragma unroll
        for (int i = tid; i < 1024; i += 128) {
            int key = i >> 4, c = i & 15;
            cpa16(sb + SMB_KS + (uint32_t)(key * 64 + 4 * (c ^ (key & 7))) * 4,
                  kg + key * DH + 4 * c);
            cpa16(sb + SMB_VS + (uint32_t)(key * 64 + 4 * c) * 4,
                  vg + key * DH + 4 * c);
        }
        asm volatile("cp.async.commit_group;");
    }

    // ---- stage Q tile as swizzled fp16 (scale folded; cvt.rn rounds) ----
#pragma unroll
    for (int i = tid; i < 2048; i += 128) {
        int row = i >> 4, c = i & 15;
        float4 t = *(const float4*)(qp + (size_t)(qs + row) * DH + 4 * c);
        uint2 wv;
        wv.x = packh2(t.x * QS2, t.y * QS2);
        wv.y = packh2(t.z * QS2, t.w * QS2);
        *(uint2*)(Qh + row * 32 + ((2 * c) ^ ((row & 7) << 2))) = wv;
    }

    float o[2][8][4];
#pragma unroll
    for (int mt = 0; mt < 2; mt++)
#pragma unroll
        for (int db = 0; db < 8; db++)
#pragma unroll
            for (int j = 0; j < 4; j++) o[mt][db][j] = 0.f;
    float mh[4] = {-1e30f, -1e30f, -1e30f, -1e30f};   // u = mt*2 + h
    float lh[4] = {0.f, 0.f, 0.f, 0.f};

    const int fix_dc = tid & 15;      // V-fixup: d-chunk
    const int fix_kq = tid >> 4;      // V-fixup: keypair group

    for (int kt = kt_lo; kt <= kt_hi; kt++) {
        asm volatile("cp.async.wait_group 0;");
        __syncthreads();    // staging ready; previous compute done

        // ---- fixup: K f32 staging -> swizzled fp16 Kh ----
#pragma unroll
        for (int i = tid; i < 1024; i += 128) {
            int key = i >> 4, c = i & 15;
            float4 t = *(const float4*)(Ks + key * 64 + 4 * (c ^ (key & 7)));
            uint2 wv;
            wv.x = packh2(t.x, t.y);
            wv.y = packh2(t.z, t.w);
            *(uint2*)(Kh + key * 32 + ((2 * c) ^ ((key & 7) << 2))) = wv;
        }
        // ---- fixup: V f32 staging -> fp16 transposed Vt[d][keypair] ----
#pragma unroll
        for (int it = 0; it < 4; it++) {
            int kp2 = fix_kq * 4 + it;          // keys 2kp2, 2kp2+1
            float4 va = *(const float4*)(Vs + (2 * kp2) * 64 + 4 * fix_dc);
            float4 vb = *(const float4*)(Vs + (2 * kp2 + 1) * 64 + 4 * fix_dc);
            float al[4] = {va.x, va.y, va.z, va.w};
            float bl[4] = {vb.x, vb.y, vb.z, vb.w};
#pragma unroll
            for (int e = 0; e < 4; e++) {
                int d = 4 * fix_dc + e;
                Vt[d * 36 + (kp2 ^ ((d >> 4) & 3))] = packh2(al[e], bl[e]);
            }
        }
        __syncthreads();    // Kh/Vt visible; staging free

        // ---- issue prefetch for next tile NOW (overlaps with compute) ----
        if (kt < kt_hi) {
            const float* kg = kp + (size_t)(kt + 1) * 64 * DH;
            const float* vg = vp + (size_t)(kt + 1) * 64 * DH;
#pragma unroll
            for (int i = tid; i < 1024; i += 128) {
                int key = i >> 4, c = i & 15;
                cpa16(sb + SMB_KS + (uint32_t)(key * 64 + 4 * (c ^ (key & 7))) * 4,
                      kg + key * DH + 4 * c);
                cpa16(sb + SMB_VS + (uint32_t)(key * 64 + 4 * c) * 4,
                      vg + key * DH + 4 * c);
            }
            asm volatile("cp.async.commit_group;");
        }

        const bool skip = (kt == 2 * qt2 + 1 && w < 2) || (kt == 2 * qt2 - 8 && w >= 2);
        if (!skip) {
            // ---- S = Q·K^T (fp16 m16n8k16, ldmatrix operands) ----
            float s[2][8][4];
#pragma unroll
            for (int mt = 0; mt < 2; mt++)
#pragma unroll
                for (int nb = 0; nb < 8; nb++)
#pragma unroll
                    for (int j = 0; j < 4; j++) s[mt][nb][j] = 0.f;
#pragma unroll
            for (int ks = 0; ks < 4; ks++) {
                const int kw = (8 * ks + k_b1) ^ l_s;     // K word offset (bits 2..4)
                const int qw = (8 * ks + q_b1) ^ l_s;     // Q word offset
                uint32_t a0[4], a1[4];
                ldsm_x4(a0, sb + SMB_QH + 4u * (uint32_t)((w * 32 + q_row) * 32 + qw));
                ldsm_x4(a1, sb + SMB_QH + 4u * (uint32_t)((w * 32 + 16 + q_row) * 32 + qw));
                const uint32_t kbase = sb + SMB_KH + 4u * (uint32_t)(k_row * 32 + kw);
#pragma unroll
                for (int g = 0; g < 4; g++) {
                    uint32_t b[4];                         // b0(2g), b1(2g), b0(2g+1), b1(2g+1)
                    ldsm_x4(b, kbase + (uint32_t)g * 2048u);
                    mma_f16(s[0][2 * g],     a0, b[0], b[1]);
                    mma_f16(s[0][2 * g + 1], a0, b[2], b[3]);
                    mma_f16(s[1][2 * g],     a1, b[0], b[1]);
                    mma_f16(s[1][2 * g + 1], a1, b[2], b[3]);
                }
            }

            // ---- boundary masks ----
            const bool do_mask = (kt == 2 * qt2 - 8) || (kt == 2 * qt2 - 7) ||
                                 (kt == 2 * qt2 && w < 2) || (kt == 2 * qt2 + 1);
            if (do_mask) {
#pragma unroll
                for (int mt = 0; mt < 2; mt++)
#pragma unroll
                    for (int nb = 0; nb < 8; nb++)
#pragma unroll
                        for (int j = 0; j < 4; j++) {
                            int cg = kt * 64 + nb * 8 + 2 * tig + (j & 1);
                            int rg = qs + w * 32 + mt * 16 + gid + 8 * (j >> 1);
                            if (cg > rg || cg < rg - (WIN - 1)) s[mt][nb][j] = -1e30f;
                        }
            }

            // ---- online softmax: 4 independent chains advanced in lockstep ----
            float mx[4], corr[4], ls[4];
#pragma unroll
            for (int u = 0; u < 4; u++) {
                const int mt = u >> 1, h = u & 1;
                float m0 = fmaxf(s[mt][0][2 * h], s[mt][0][2 * h + 1]);
                float m1 = fmaxf(s[mt][1][2 * h], s[mt][1][2 * h + 1]);
                float m2 = fmaxf(s[mt][2][2 * h], s[mt][2][2 * h + 1]);
                float m3 = fmaxf(s[mt][3][2 * h], s[mt][3][2 * h + 1]);
                float m4 = fmaxf(s[mt][4][2 * h], s[mt][4][2 * h + 1]);
                float m5 = fmaxf(s[mt][5][2 * h], s[mt][5][2 * h + 1]);
                float m6 = fmaxf(s[mt][6][2 * h], s[mt][6][2 * h + 1]);
                float m7 = fmaxf(s[mt][7][2 * h], s[mt][7][2 * h + 1]);
                mx[u] = fmaxf(fmaxf(fmaxf(m0, m1), fmaxf(m2, m3)),
                              fmaxf(fmaxf(m4, m5), fmaxf(m6, m7)));
            }
#pragma unroll
            for (int u = 0; u < 4; u++) mx[u] = fmaxf(mx[u], __shfl_xor_sync(0xffffffffu, mx[u], 1));
#pragma unroll
            for (int u = 0; u < 4; u++) mx[u] = fmaxf(mx[u], __shfl_xor_sync(0xffffffffu, mx[u], 2));
#pragma unroll
            for (int u = 0; u < 4; u++) {
                float mn = fmaxf(mh[u], mx[u]);
                corr[u] = ex2f(mh[u] - mn);
                mh[u] = mn;
            }
#pragma unroll
            for (int u = 0; u < 4; u++) {
                const int mt = u >> 1, h = u & 1;
                float acc0 = 0.f, acc1 = 0.f;
#pragma unroll
                for (int nb = 0; nb < 8; nb++) {
                    float p0 = ex2f(s[mt][nb][2 * h]     - mh[u]);
                    float p1 = ex2f(s[mt][nb][2 * h + 1] - mh[u]);
                    s[mt][nb][2 * h]     = p0;
                    s[mt][nb][2 * h + 1] = p1;
                    acc0 += p0; acc1 += p1;
                }
                ls[u] = acc0 + acc1;
            }
#pragma unroll
            for (int u = 0; u < 4; u++) ls[u] += __shfl_xor_sync(0xffffffffu, ls[u], 1);
#pragma unroll
            for (int u = 0; u < 4; u++) ls[u] += __shfl_xor_sync(0xffffffffu, ls[u], 2);
#pragma unroll
            for (int u = 0; u < 4; u++) {
                const int mt = u >> 1, h = u & 1;
                lh[u] = lh[u] * corr[u] + ls[u];
#pragma unroll
                for (int db = 0; db < 8; db++) {
                    o[mt][db][2 * h]     *= corr[u];
                    o[mt][db][2 * h + 1] *= corr[u];
                }
            }

            // ---- O += P·V : fp16 m16n8k16, P C-frags pack directly into A-frags ----
#pragma unroll
            for (int j = 0; j < 4; j++) {
                uint32_t ap0[4], ap1[4];
                ap0[0] = packh2(s[0][2 * j][0],     s[0][2 * j][1]);
                ap0[1] = packh2(s[0][2 * j][2],     s[0][2 * j][3]);
                ap0[2] = packh2(s[0][2 * j + 1][0], s[0][2 * j + 1][1]);
                ap0[3] = packh2(s[0][2 * j + 1][2], s[0][2 * j + 1][3]);
                ap1[0] = packh2(s[1][2 * j][0],     s[1][2 * j][1]);
                ap1[1] = packh2(s[1][2 * j][2],     s[1][2 * j][3]);
                ap1[2] = packh2(s[1][2 * j + 1][0], s[1][2 * j + 1][1]);
                ap1[3] = packh2(s[1][2 * j + 1][2], s[1][2 * j + 1][3]);
#pragma unroll
                for (int db = 0; db < 8; db++) {
                    int d = db * 8 + gid;
                    int f = (d >> 4) & 3;
                    uint32_t b0 = Vt[d * 36 + ((8 * j + tig) ^ f)];
                    uint32_t b1 = Vt[d * 36 + ((8 * j + tig + 4) ^ f)];
                    mma_f16(o[0][db], ap0, b0, b1);
                    mma_f16(o[1][db], ap1, b0, b1);
                }
            }
        }
        // no tail sync: loop-head sync after wait_group covers the hazard
    }

    // ---- epilogue ----
#pragma unroll
    for (int mt = 0; mt < 2; mt++) {
        const int rl0 = w * 32 + mt * 16 + gid;
        float inv0 = 1.0f / lh[2 * mt];
        float inv1 = 1.0f / lh[2 * mt + 1];
        float* op = out + ((size_t)bh * NQ + qs + rl0) * DH;
#pragma unroll
        for (int db = 0; db < 8; db++) {
            *(float2*)(op + db * 8 + 2 * tig) =
                make_float2(o[mt][db][0] * inv0, o[mt][db][1] * inv0);
            *(float2*)(op + 8 * DH + db * 8 + 2 * tig) =
                make_float2(o[mt][db][2] * inv1, o[mt][db][3] * inv1);
        }
    }
}

extern "C" void kernel_launch(void* const* d_in, const int* in_sizes, int n_in,
                              void* d_out, int out_size)
{
    const float* q = (const float*)d_in[0];
    const float* k = (const float*)d_in[1];
    const float* v = (const float*)d_in[2];
    float* o = (float*)d_out;

    cudaFuncSetAttribute(swa_mma_kernel, cudaFuncAttributeMaxDynamicSharedMemorySize, SMB_TOT);
    dim3 grid(NQ / QT, 32);   // (16 query tiles, B*H)
    swa_mma_kernel<<<grid, 128, SMB_TOT>>>(q, k, v, o);
}

// round 10
// speedup vs baseline: 1.3704x; 1.3704x over previous
#include <cuda_runtime.h>
#include <cuda_fp16.h>
#include <cstdint>

#define NQ  2048
#define DH  64
#define WIN 512
#define QT  128
// 0.125 * log2(e) folded into Q; softmax in log2 domain via ex2.approx
#define QS2 0.18033688011112042f

// byte offsets in dynamic smem (total 66560 B -> 3 CTAs/SM)
#define SMB_QH  0        // 128 rows x 32 u32 (fp16x2), word ^ ((row&7)<<2)
#define SMB_KH  16384    // 64 keys x 32 u32 (fp16x2), same swizzle
#define SMB_VT  24576    // Vt fp16 [d][keypair], stride 36 u32, kp ^ ((d>>4)&3)
#define SMB_KS  33792    // K f32 staging 64x64, chunk ^ (key&7)
#define SMB_VS  50176    // V f32 staging 64x64, plain
#define SMB_TOT 66560

static __device__ __forceinline__ float ex2f(float x) {
    float y; asm("ex2.approx.f32 %0, %1;" : "=f"(y) : "f"(x)); return y;
}
static __device__ __forceinline__ uint32_t packh2(float lo, float hi) {
    __half2 h = __floats2half2_rn(lo, hi);
    return *(uint32_t*)&h;
}
static __device__ __forceinline__ void mma_f16(float* d, const uint32_t* a,
                                               uint32_t b0, uint32_t b1) {
    asm volatile(
        "mma.sync.aligned.m16n8k16.row.col.f32.f16.f16.f32 "
        "{%0,%1,%2,%3}, {%4,%5,%6,%7}, {%8,%9}, {%0,%1,%2,%3};"
        : "+f"(d[0]), "+f"(d[1]), "+f"(d[2]), "+f"(d[3])
        : "r"(a[0]), "r"(a[1]), "r"(a[2]), "r"(a[3]), "r"(b0), "r"(b1));
}
static __device__ __forceinline__ uint32_t smem_u32(const void* p) {
    uint32_t a;
    asm("{ .reg .u64 t; cvta.to.shared.u64 t, %1; cvt.u32.u64 %0, t; }" : "=r"(a) : "l"(p));
    return a;
}
static __device__ __forceinline__ void cpa16(uint32_t dst, const float* src) {
    asm volatile("cp.async.cg.shared.global [%0], [%1], 16;" :: "r"(dst), "l"(src));
}

__global__ __launch_bounds__(128, 3)
void swa_mma_kernel(const float* __restrict__ q, const float* __restrict__ k,
                    const float* __restrict__ v, float* __restrict__ out)
{
    extern __shared__ char smc[];
    const uint32_t sb = smem_u32(smc);
    uint32_t* Qh = (uint32_t*)(smc + SMB_QH);
    uint32_t* Kh = (uint32_t*)(smc + SMB_KH);
    uint32_t* Vt = (uint32_t*)(smc + SMB_VT);
    float*    Ks = (float*)(smc + SMB_KS);
    float*    Vs = (float*)(smc + SMB_VS);

    const int tid  = threadIdx.x;
    const int w    = tid >> 5;
    const int lane = tid & 31;
    const int gid  = lane >> 2;
    const int tig  = lane & 3;

    const int qt2 = (int)gridDim.x - 1 - (int)blockIdx.x;   // long CTAs first
    const int bh  = blockIdx.y;
    const int qs  = qt2 * QT;

    const float* qp = q + (size_t)bh * NQ * DH;
    const float* kp = k + (size_t)bh * NQ * DH;
    const float* vp = v + (size_t)bh * NQ * DH;

    const int kt_lo = (2 * qt2 - 8) > 0 ? (2 * qt2 - 8) : 0;
    const int kt_hi = 2 * qt2 + 1;

    // ---- prefetch first K/V tile into staging ----
    {
        const float* kg = kp + (size_t)kt_lo * 64 * DH;
        const float* vg = vp + (size_t)kt_lo * 64 * DH;
#pragma unroll
        for (int i = tid; i < 1024; i += 128) {
            int key = i >> 4, c = i & 15;
            cpa16(sb + SMB_KS + (uint32_t)(key * 64 + 4 * (c ^ (key & 7))) * 4,
                  kg + key * DH + 4 * c);
            cpa16(sb + SMB_VS + (uint32_t)(key * 64 + 4 * c) * 4,
                  vg + key * DH + 4 * c);
        }
        asm volatile("cp.async.commit_group;");
    }

    // ---- stage Q tile as swizzled fp16 (scale folded; cvt.rn rounds) ----
#pragma unroll
    for (int i = tid; i < 2048; i += 128) {
        int row = i >> 4, c = i & 15;
        float4 t = *(const float4*)(qp + (size_t)(qs + row) * DH + 4 * c);
        uint2 wv;
        wv.x = packh2(t.x * QS2, t.y * QS2);
        wv.y = packh2(t.z * QS2, t.w * QS2);
        *(uint2*)(Qh + row * 32 + ((2 * c) ^ ((row & 7) << 2))) = wv;
    }

    float o[2][8][4];
#pragma unroll
    for (int mt = 0; mt < 2; mt++)
#pragma unroll
        for (int db = 0; db < 8; db++)
#pragma unroll
            for (int j = 0; j < 4; j++) o[mt][db][j] = 0.f;
    float mh[4] = {-1e30f, -1e30f, -1e30f, -1e30f};   // u = mt*2 + h
    float lh[4] = {0.f, 0.f, 0.f, 0.f};

    const int fix_dc = tid & 15;      // V-fixup: d-chunk
    const int fix_kq = tid >> 4;      // V-fixup: keypair group

    for (int kt = kt_lo; kt <= kt_hi; kt++) {
        asm volatile("cp.async.wait_group 0;");
        __syncthreads();    // staging ready; previous compute done

        // ---- fixup: K f32 staging -> swizzled fp16 Kh ----
#pragma unroll
        for (int i = tid; i < 1024; i += 128) {
            int key = i >> 4, c = i & 15;
            float4 t = *(const float4*)(Ks + key * 64 + 4 * (c ^ (key & 7)));
            uint2 wv;
            wv.x = packh2(t.x, t.y);
            wv.y = packh2(t.z, t.w);
            *(uint2*)(Kh + key * 32 + ((2 * c) ^ ((key & 7) << 2))) = wv;
        }
        // ---- fixup: V f32 staging -> fp16 transposed Vt[d][keypair] ----
#pragma unroll
        for (int it = 0; it < 4; it++) {
            int kp2 = fix_kq * 4 + it;          // keys 2kp2, 2kp2+1
            float4 va = *(const float4*)(Vs + (2 * kp2) * 64 + 4 * fix_dc);
            float4 vb = *(const float4*)(Vs + (2 * kp2 + 1) * 64 + 4 * fix_dc);
            float al[4] = {va.x, va.y, va.z, va.w};
            float bl[4] = {vb.x, vb.y, vb.z, vb.w};
#pragma unroll
            for (int e = 0; e < 4; e++) {
                int d = 4 * fix_dc + e;
                Vt[d * 36 + (kp2 ^ ((d >> 4) & 3))] = packh2(al[e], bl[e]);
            }
        }
        __syncthreads();    // Kh/Vt visible; staging free

        // ---- issue prefetch for next tile NOW (overlaps with compute) ----
        if (kt < kt_hi) {
            const float* kg = kp + (size_t)(kt + 1) * 64 * DH;
            const float* vg = vp + (size_t)(kt + 1) * 64 * DH;
#pragma unroll
            for (int i = tid; i < 1024; i += 128) {
                int key = i >> 4, c = i & 15;
                cpa16(sb + SMB_KS + (uint32_t)(key * 64 + 4 * (c ^ (key & 7))) * 4,
                      kg + key * DH + 4 * c);
                cpa16(sb + SMB_VS + (uint32_t)(key * 64 + 4 * c) * 4,
                      vg + key * DH + 4 * c);
            }
            asm volatile("cp.async.commit_group;");
        }

        const bool skip = (kt == 2 * qt2 + 1 && w < 2) || (kt == 2 * qt2 - 8 && w >= 2);
        if (!skip) {
            // ---- S = Q·K^T (fp16 m16n8k16, 4 k-steps; scalar LDS fragments) ----
            float s[2][8][4];
#pragma unroll
            for (int mt = 0; mt < 2; mt++)
#pragma unroll
                for (int nb = 0; nb < 8; nb++)
#pragma unroll
                    for (int j = 0; j < 4; j++) s[mt][nb][j] = 0.f;
#pragma unroll
            for (int ks = 0; ks < 4; ks++) {
                const int dp0 = (8 * ks + tig) ^ (gid << 2);
                const int dp1 = (8 * ks + tig + 4) ^ (gid << 2);
                const int qr = (w * 32 + gid) * 32;
                uint32_t a0[4], a1[4];
                a0[0] = Qh[qr + dp0];
                a0[1] = Qh[qr + 8 * 32 + dp0];
                a0[2] = Qh[qr + dp1];
                a0[3] = Qh[qr + 8 * 32 + dp1];
                a1[0] = Qh[qr + 16 * 32 + dp0];
                a1[1] = Qh[qr + 24 * 32 + dp0];
                a1[2] = Qh[qr + 16 * 32 + dp1];
                a1[3] = Qh[qr + 24 * 32 + dp1];
#pragma unroll
                for (int nb = 0; nb < 8; nb++) {
                    uint32_t b0 = Kh[(nb * 8 + gid) * 32 + dp0];
                    uint32_t b1 = Kh[(nb * 8 + gid) * 32 + dp1];
                    mma_f16(s[0][nb], a0, b0, b1);
                    mma_f16(s[1][nb], a1, b0, b1);
                }
            }

            // ---- boundary masks ----
            const bool do_mask = (kt == 2 * qt2 - 8) || (kt == 2 * qt2 - 7) ||
                                 (kt == 2 * qt2 && w < 2) || (kt == 2 * qt2 + 1);
            if (do_mask) {
#pragma unroll
                for (int mt = 0; mt < 2; mt++)
#pragma unroll
                    for (int nb = 0; nb < 8; nb++)
#pragma unroll
                        for (int j = 0; j < 4; j++) {
                            int cg = kt * 64 + nb * 8 + 2 * tig + (j & 1);
                            int rg = qs + w * 32 + mt * 16 + gid + 8 * (j >> 1);
                            if (cg > rg || cg < rg - (WIN - 1)) s[mt][nb][j] = -1e30f;
                        }
            }

            // ---- online softmax: 4 independent chains advanced in lockstep ----
            float mx[4], corr[4], ls[4];
#pragma unroll
            for (int u = 0; u < 4; u++) {
                const int mt = u >> 1, h = u & 1;
                float m0 = fmaxf(s[mt][0][2 * h], s[mt][0][2 * h + 1]);
                float m1 = fmaxf(s[mt][1][2 * h], s[mt][1][2 * h + 1]);
                float m2 = fmaxf(s[mt][2][2 * h], s[mt][2][2 * h + 1]);
                float m3 = fmaxf(s[mt][3][2 * h], s[mt][3][2 * h + 1]);
                float m4 = fmaxf(s[mt][4][2 * h], s[mt][4][2 * h + 1]);
                float m5 = fmaxf(s[mt][5][2 * h], s[mt][5][2 * h + 1]);
                float m6 = fmaxf(s[mt][6][2 * h], s[mt][6][2 * h + 1]);
                float m7 = fmaxf(s[mt][7][2 * h], s[mt][7][2 * h + 1]);
                mx[u] = fmaxf(fmaxf(fmaxf(m0, m1), fmaxf(m2, m3)),
                              fmaxf(fmaxf(m4, m5), fmaxf(m6, m7)));
            }
#pragma unroll
            for (int u = 0; u < 4; u++) mx[u] = fmaxf(mx[u], __shfl_xor_sync(0xffffffffu, mx[u], 1));
#pragma unroll
            for (int u = 0; u < 4; u++) mx[u] = fmaxf(mx[u], __shfl_xor_sync(0xffffffffu, mx[u], 2));
#pragma unroll
            for (int u = 0; u < 4; u++) {
                float mn = fmaxf(mh[u], mx[u]);
                corr[u] = ex2f(mh[u] - mn);
                mh[u] = mn;
            }
#pragma unroll
            for (int u = 0; u < 4; u++) {
                const int mt = u >> 1, h = u & 1;
                float acc0 = 0.f, acc1 = 0.f;
#pragma unroll
                for (int nb = 0; nb < 8; nb++) {
                    float p0 = ex2f(s[mt][nb][2 * h]     - mh[u]);
                    float p1 = ex2f(s[mt][nb][2 * h + 1] - mh[u]);
                    s[mt][nb][2 * h]     = p0;
                    s[mt][nb][2 * h + 1] = p1;
                    acc0 += p0; acc1 += p1;
                }
                ls[u] = acc0 + acc1;
            }
#pragma unroll
            for (int u = 0; u < 4; u++) ls[u] += __shfl_xor_sync(0xffffffffu, ls[u], 1);
#pragma unroll
            for (int u = 0; u < 4; u++) ls[u] += __shfl_xor_sync(0xffffffffu, ls[u], 2);
#pragma unroll
            for (int u = 0; u < 4; u++) {
                const int mt = u >> 1, h = u & 1;
                lh[u] = lh[u] * corr[u] + ls[u];
#pragma unroll
                for (int db = 0; db < 8; db++) {
                    o[mt][db][2 * h]     *= corr[u];
                    o[mt][db][2 * h + 1] *= corr[u];
                }
            }

            // ---- O += P·V : fp16 m16n8k16, P C-frags pack directly into A-frags ----
#pragma unroll
            for (int j = 0; j < 4; j++) {
                uint32_t ap0[4], ap1[4];
                ap0[0] = packh2(s[0][2 * j][0],     s[0][2 * j][1]);
                ap0[1] = packh2(s[0][2 * j][2],     s[0][2 * j][3]);
                ap0[2] = packh2(s[0][2 * j + 1][0], s[0][2 * j + 1][1]);
                ap0[3] = packh2(s[0][2 * j + 1][2], s[0][2 * j + 1][3]);
                ap1[0] = packh2(s[1][2 * j][0],     s[1][2 * j][1]);
                ap1[1] = packh2(s[1][2 * j][2],     s[1][2 * j][3]);
                ap1[2] = packh2(s[1][2 * j + 1][0], s[1][2 * j + 1][1]);
                ap1[3] = packh2(s[1][2 * j + 1][2], s[1][2 * j + 1][3]);
#pragma unroll
                for (int db = 0; db < 8; db++) {
                    int d = db * 8 + gid;
                    int f = (d >> 4) & 3;
                    uint32_t b0 = Vt[d * 36 + ((8 * j + tig) ^ f)];
                    uint32_t b1 = Vt[d * 36 + ((8 * j + tig + 4) ^ f)];
                    mma_f16(o[0][db], ap0, b0, b1);
                    mma_f16(o[1][db], ap1, b0, b1);
                }
            }
        }
        // no tail sync: loop-head sync after wait_group covers the hazard
    }

    // ---- epilogue ----
#pragma unroll
    for (int mt = 0; mt < 2; mt++) {
        const int rl0 = w * 32 + mt * 16 + gid;
        float inv0 = 1.0f / lh[2 * mt];
        float inv1 = 1.0f / lh[2 * mt + 1];
        float* op = out + ((size_t)bh * NQ + qs + rl0) * DH;
#pragma unroll
        for (int db = 0; db < 8; db++) {
            *(float2*)(op + db * 8 + 2 * tig) =
                make_float2(o[mt][db][0] * inv0, o[mt][db][1] * inv0);
            *(float2*)(op + 8 * DH + db * 8 + 2 * tig) =
                make_float2(o[mt][db][2] * inv1, o[mt][db][3] * inv1);
        }
    }
}

extern "C" void kernel_launch(void* const* d_in, const int* in_sizes, int n_in,
                              void* d_out, int out_size)
{
    const float* q = (const float*)d_in[0];
    const float* k = (const float*)d_in[1];
    const float* v = (const float*)d_in[2];
    float* o = (float*)d_out;

    cudaFuncSetAttribute(swa_mma_kernel, cudaFuncAttributeMaxDynamicSharedMemorySize, SMB_TOT);
    dim3 grid(NQ / QT, 32);   // (16 query tiles, B*H)
    swa_mma_kernel<<<grid, 128, SMB_TOT>>>(q, k, v, o);
}

// round 11
// speedup vs baseline: 1.5550x; 1.1347x over previous
#include <cuda_runtime.h>
#include <cuda_fp16.h>
#include <cstdint>

#define NQ  2048
#define DH  64
#define WIN 512
#define QT  128
// 0.125 * log2(e) folded into Q; softmax in log2 domain via ex2.approx
#define QS2 0.18033688011112042f

// smem byte offsets (total 83968 B -> 2 CTAs/SM at 256 threads)
#define SMB_QH  0        // 128 rows x 32 u32 (fp16x2), word ^ ((row&7)<<2)
#define SMB_KS  16384    // K f32 staging 64x64, 16B-chunk ^ (key&7)
#define SMB_VS  32768    // V f32 staging 64x64, plain
#define SMB_KH0 49152    // 64 keys x 32 u32 fp16x2 (same swizzle as QH)
#define SMB_KH1 57344
#define SMB_VT0 65536    // Vt fp16 [d][keypair], stride 36 u32, kp ^ ((d>>4)&3)
#define SMB_VT1 74752
#define SMB_TOT 83968

static __device__ __forceinline__ float ex2f(float x) {
    float y; asm("ex2.approx.f32 %0, %1;" : "=f"(y) : "f"(x)); return y;
}
static __device__ __forceinline__ uint32_t packh2(float lo, float hi) {
    __half2 h = __floats2half2_rn(lo, hi);
    return *(uint32_t*)&h;
}
static __device__ __forceinline__ void mma_f16(float* d, const uint32_t* a,
                                               uint32_t b0, uint32_t b1) {
    asm volatile(
        "mma.sync.aligned.m16n8k16.row.col.f32.f16.f16.f32 "
        "{%0,%1,%2,%3}, {%4,%5,%6,%7}, {%8,%9}, {%0,%1,%2,%3};"
        : "+f"(d[0]), "+f"(d[1]), "+f"(d[2]), "+f"(d[3])
        : "r"(a[0]), "r"(a[1]), "r"(a[2]), "r"(a[3]), "r"(b0), "r"(b1));
}
static __device__ __forceinline__ uint32_t smem_u32(const void* p) {
    uint32_t a;
    asm("{ .reg .u64 t; cvta.to.shared.u64 t, %1; cvt.u32.u64 %0, t; }" : "=r"(a) : "l"(p));
    return a;
}
static __device__ __forceinline__ void cpa16(uint32_t dst, const float* src) {
    asm volatile("cp.async.cg.shared.global [%0], [%1], 16;" :: "r"(dst), "l"(src));
}

__global__ __launch_bounds__(256, 2)
void swa_mma_kernel(const float* __restrict__ q, const float* __restrict__ k,
                    const float* __restrict__ v, float* __restrict__ out)
{
    extern __shared__ char smc[];
    const uint32_t sb = smem_u32(smc);
    uint32_t* Qh = (uint32_t*)(smc + SMB_QH);
    float*    Ks = (float*)(smc + SMB_KS);
    float*    Vs = (float*)(smc + SMB_VS);

    const int tid  = threadIdx.x;
    const int w    = tid >> 5;       // 0..7, one m16 tile each
    const int lane = tid & 31;
    const int gid  = lane >> 2;
    const int tig  = lane & 3;

    const int qt2 = (int)gridDim.x - 1 - (int)blockIdx.x;   // long CTAs first
    const int bh  = blockIdx.y;
    const int qs  = qt2 * QT;

    const float* qp = q + (size_t)bh * NQ * DH;
    const float* kp = k + (size_t)bh * NQ * DH;
    const float* vp = v + (size_t)bh * NQ * DH;

    const int kt_lo = (2 * qt2 - 8) > 0 ? (2 * qt2 - 8) : 0;
    const int kt_hi = 2 * qt2 + 1;

    // staging cell ownership (identical maps in prefetch and convert)
    const int sc  = tid & 15;        // 16B col-chunk
    const int sk0 = tid >> 4;        // base key / keypair group

    // ---- prefetch(kt) into staging: K swizzled chunks, V plain ----
    auto prefetch = [&](int kt) {
        const float* kg = kp + (size_t)kt * 64 * DH;
        const float* vg = vp + (size_t)kt * 64 * DH;
#pragma unroll
        for (int it = 0; it < 4; it++) {
            int key = sk0 + 16 * it;
            cpa16(sb + SMB_KS + (uint32_t)(key * 64 + 4 * (sc ^ (key & 7))) * 4,
                  kg + key * DH + 4 * sc);
        }
#pragma unroll
        for (int it = 0; it < 2; it++) {
            int b = sk0 + 16 * it;
            cpa16(sb + SMB_VS + (uint32_t)((2 * b) * 64 + 4 * sc) * 4,
                  vg + (2 * b) * DH + 4 * sc);
            cpa16(sb + SMB_VS + (uint32_t)((2 * b + 1) * 64 + 4 * sc) * 4,
                  vg + (2 * b + 1) * DH + 4 * sc);
        }
        asm volatile("cp.async.commit_group;");
    };

    // ---- convert staging -> fp16 Kh + transposed Vt (self-owned cells) ----
    auto convert = [&](uint32_t* KHd, uint32_t* VTd) {
#pragma unroll
        for (int it = 0; it < 4; it++) {
            int key = sk0 + 16 * it;
            float4 t = *(const float4*)(Ks + key * 64 + 4 * (sc ^ (key & 7)));
            uint2 wv;
            wv.x = packh2(t.x, t.y);
            wv.y = packh2(t.z, t.w);
            *(uint2*)(KHd + key * 32 + ((2 * sc) ^ ((key & 7) << 2))) = wv;
        }
#pragma unroll
        for (int it = 0; it < 2; it++) {
            int b = sk0 + 16 * it;
            float4 va = *(const float4*)(Vs + (2 * b) * 64 + 4 * sc);
            float4 vb = *(const float4*)(Vs + (2 * b + 1) * 64 + 4 * sc);
            float al[4] = {va.x, va.y, va.z, va.w};
            float bl[4] = {vb.x, vb.y, vb.z, vb.w};
#pragma unroll
            for (int e = 0; e < 4; e++) {
                int d = 4 * sc + e;
                VTd[d * 36 + (b ^ ((d >> 4) & 3))] = packh2(al[e], bl[e]);
            }
        }
    };

    // ---- prologue: prefetch t0, stage Q, convert t0, prefetch t1 ----
    prefetch(kt_lo);
#pragma unroll
    for (int i = tid; i < 2048; i += 256) {
        int row = i >> 4, c = i & 15;
        float4 t = *(const float4*)(qp + (size_t)(qs + row) * DH + 4 * c);
        uint2 wv;
        wv.x = packh2(t.x * QS2, t.y * QS2);
        wv.y = packh2(t.z * QS2, t.w * QS2);
        *(uint2*)(Qh + row * 32 + ((2 * c) ^ ((row & 7) << 2))) = wv;
    }
    asm volatile("cp.async.wait_group 0;");
    __syncthreads();
    convert((uint32_t*)(smc + SMB_KH0), (uint32_t*)(smc + SMB_VT0));
    if (kt_lo + 1 <= kt_hi) prefetch(kt_lo + 1);
    __syncthreads();

    float o[8][4];
#pragma unroll
    for (int db = 0; db < 8; db++)
#pragma unroll
        for (int j = 0; j < 4; j++) o[db][j] = 0.f;
    float mh[2] = {-1e30f, -1e30f};
    float lh[2] = {0.f, 0.f};

    int x = 0;
    for (int kt = kt_lo; kt <= kt_hi; kt++) {
        const uint32_t* KH = (const uint32_t*)(smc + (x ? SMB_KH1 : SMB_KH0));
        const uint32_t* VT = (const uint32_t*)(smc + (x ? SMB_VT1 : SMB_VT0));

        // ---- pipelined: convert kt+1 into idle buffer, issue prefetch kt+2 ----
        if (kt + 1 <= kt_hi) {
            asm volatile("cp.async.wait_group 0;");   // staging(kt+1) arrived
            convert((uint32_t*)(smc + (x ? SMB_KH0 : SMB_KH1)),
                    (uint32_t*)(smc + (x ? SMB_VT0 : SMB_VT1)));
            if (kt + 2 <= kt_hi) prefetch(kt + 2);    // same-thread cells: no barrier
        }

        // warp fully-masked tile skip (rows<64 at causal edge / rows>=64 at window edge)
        const bool skip = (kt == 2 * qt2 + 1 && w < 4) || (kt == 2 * qt2 - 8 && w >= 4);
        if (!skip) {
            // ---- S = Q·K^T (fp16 m16n8k16, scalar LDS fragments) ----
            float s[8][4];
#pragma unroll
            for (int nb = 0; nb < 8; nb++)
#pragma unroll
                for (int j = 0; j < 4; j++) s[nb][j] = 0.f;
#pragma unroll
            for (int ks = 0; ks < 4; ks++) {
                const int dp0 = (8 * ks + tig) ^ (gid << 2);
                const int dp1 = (8 * ks + tig + 4) ^ (gid << 2);
                const int qr = (16 * w + gid) * 32;
                uint32_t a0[4];
                a0[0] = Qh[qr + dp0];
                a0[1] = Qh[qr + 8 * 32 + dp0];
                a0[2] = Qh[qr + dp1];
                a0[3] = Qh[qr + 8 * 32 + dp1];
#pragma unroll
                for (int nb = 0; nb < 8; nb++) {
                    uint32_t b0 = KH[(nb * 8 + gid) * 32 + dp0];
                    uint32_t b1 = KH[(nb * 8 + gid) * 32 + dp1];
                    mma_f16(s[nb], a0, b0, b1);
                }
            }

            // ---- boundary masks ----
            const bool do_mask = (kt == 2 * qt2 - 8) || (kt == 2 * qt2 - 7) ||
                                 (kt == 2 * qt2 && w < 4) || (kt == 2 * qt2 + 1);
            if (do_mask) {
#pragma unroll
                for (int nb = 0; nb < 8; nb++)
#pragma unroll
                    for (int j = 0; j < 4; j++) {
                        int cg = kt * 64 + nb * 8 + 2 * tig + (j & 1);
                        int rg = qs + 16 * w + gid + 8 * (j >> 1);
                        if (cg > rg || cg < rg - (WIN - 1)) s[nb][j] = -1e30f;
                    }
            }

            // ---- online softmax (log2 domain), 2 chains in lockstep ----
            float mx[2], corr[2], ls[2];
#pragma unroll
            for (int u = 0; u < 2; u++) {
                float m0 = fmaxf(s[0][2 * u], s[0][2 * u + 1]);
                float m1 = fmaxf(s[1][2 * u], s[1][2 * u + 1]);
                float m2 = fmaxf(s[2][2 * u], s[2][2 * u + 1]);
                float m3 = fmaxf(s[3][2 * u], s[3][2 * u + 1]);
                float m4 = fmaxf(s[4][2 * u], s[4][2 * u + 1]);
                float m5 = fmaxf(s[5][2 * u], s[5][2 * u + 1]);
                float m6 = fmaxf(s[6][2 * u], s[6][2 * u + 1]);
                float m7 = fmaxf(s[7][2 * u], s[7][2 * u + 1]);
                mx[u] = fmaxf(fmaxf(fmaxf(m0, m1), fmaxf(m2, m3)),
                              fmaxf(fmaxf(m4, m5), fmaxf(m6, m7)));
            }
#pragma unroll
            for (int u = 0; u < 2; u++) mx[u] = fmaxf(mx[u], __shfl_xor_sync(0xffffffffu, mx[u], 1));
#pragma unroll
            for (int u = 0; u < 2; u++) mx[u] = fmaxf(mx[u], __shfl_xor_sync(0xffffffffu, mx[u], 2));
#pragma unroll
            for (int u = 0; u < 2; u++) {
                float mn = fmaxf(mh[u], mx[u]);
                corr[u] = ex2f(mh[u] - mn);
                mh[u] = mn;
            }
#pragma unroll
            for (int u = 0; u < 2; u++) {
                float acc0 = 0.f, acc1 = 0.f;
#pragma unroll
                for (int nb = 0; nb < 8; nb++) {
                    float p0 = ex2f(s[nb][2 * u]     - mh[u]);
                    float p1 = ex2f(s[nb][2 * u + 1] - mh[u]);
                    s[nb][2 * u]     = p0;
                    s[nb][2 * u + 1] = p1;
                    acc0 += p0; acc1 += p1;
                }
                ls[u] = acc0 + acc1;
            }
#pragma unroll
            for (int u = 0; u < 2; u++) ls[u] += __shfl_xor_sync(0xffffffffu, ls[u], 1);
#pragma unroll
            for (int u = 0; u < 2; u++) ls[u] += __shfl_xor_sync(0xffffffffu, ls[u], 2);
#pragma unroll
            for (int u = 0; u < 2; u++) {
                lh[u] = lh[u] * corr[u] + ls[u];
#pragma unroll
                for (int db = 0; db < 8; db++) {
                    o[db][2 * u]     *= corr[u];
                    o[db][2 * u + 1] *= corr[u];
                }
            }

            // ---- O += P·V (fp16, P C-frags pack directly into A-frags) ----
#pragma unroll
            for (int j = 0; j < 4; j++) {
                uint32_t ap[4];
                ap[0] = packh2(s[2 * j][0],     s[2 * j][1]);
                ap[1] = packh2(s[2 * j][2],     s[2 * j][3]);
                ap[2] = packh2(s[2 * j + 1][0], s[2 * j + 1][1]);
                ap[3] = packh2(s[2 * j + 1][2], s[2 * j + 1][3]);
#pragma unroll
                for (int db = 0; db < 8; db++) {
                    int d = db * 8 + gid;
                    int f = (d >> 4) & 3;
                    uint32_t b0 = VT[d * 36 + ((8 * j + tig) ^ f)];
                    uint32_t b1 = VT[d * 36 + ((8 * j + tig + 4) ^ f)];
                    mma_f16(o[db], ap, b0, b1);
                }
            }
        }
        __syncthreads();    // single barrier: publishes converted buf, retires current buf
        x ^= 1;
    }

    // ---- epilogue ----
    {
        const int rl0 = 16 * w + gid;
        float inv0 = 1.0f / lh[0];
        float inv1 = 1.0f / lh[1];
        float* op = out + ((size_t)bh * NQ + qs + rl0) * DH;
#pragma unroll
        for (int db = 0; db < 8; db++) {
            *(float2*)(op + db * 8 + 2 * tig) =
                make_float2(o[db][0] * inv0, o[db][1] * inv0);
            *(float2*)(op + 8 * DH + db * 8 + 2 * tig) =
                make_float2(o[db][2] * inv1, o[db][3] * inv1);
        }
    }
}

extern "C" void kernel_launch(void* const* d_in, const int* in_sizes, int n_in,
                              void* d_out, int out_size)
{
    const float* q = (const float*)d_in[0];
    const float* k = (const float*)d_in[1];
    const float* v = (const float*)d_in[2];
    float* o = (float*)d_out;

    cudaFuncSetAttribute(swa_mma_kernel, cudaFuncAttributeMaxDynamicSharedMemorySize, SMB_TOT);
    dim3 grid(NQ / QT, 32);   // (16 query tiles, B*H)
    swa_mma_kernel<<<grid, 256, SMB_TOT>>>(q, k, v, o);
}

// round 12
// speedup vs baseline: 1.5953x; 1.0259x over previous
#include <cuda_runtime.h>
#include <cuda_fp16.h>
#include <cstdint>

#define NQ  2048
#define DH  64
#define WIN 512
#define QT  128
// 0.125 * log2(e) folded into Q; softmax in log2 domain via ex2.approx
#define QS2 0.18033688011112042f

// smem byte offsets (total 83968 B -> 2 CTAs/SM at 256 threads)
#define SMB_QH  0        // 128 rows x 32 u32 (fp16x2), word ^ ((row&7)<<2)
#define SMB_KS  16384    // K f32 staging 64x64, 16B-chunk ^ (key&7)
#define SMB_VS  32768    // V f32 staging 64x64, plain
#define SMB_KH0 49152    // 64 keys x 32 u32 fp16x2 (same swizzle as QH)
#define SMB_KH1 57344
#define SMB_VT0 65536    // Vt fp16 [d][keypair], stride 36 u32, kp ^ ((d>>4)&3)
#define SMB_VT1 74752
#define SMB_TOT 83968

static __device__ __forceinline__ float ex2f(float x) {
    float y; asm("ex2.approx.f32 %0, %1;" : "=f"(y) : "f"(x)); return y;
}
static __device__ __forceinline__ uint32_t packh2(float lo, float hi) {
    __half2 h = __floats2half2_rn(lo, hi);
    return *(uint32_t*)&h;
}
static __device__ __forceinline__ void mma_f16(float* d, const uint32_t* a,
                                               uint32_t b0, uint32_t b1) {
    asm volatile(
        "mma.sync.aligned.m16n8k16.row.col.f32.f16.f16.f32 "
        "{%0,%1,%2,%3}, {%4,%5,%6,%7}, {%8,%9}, {%0,%1,%2,%3};"
        : "+f"(d[0]), "+f"(d[1]), "+f"(d[2]), "+f"(d[3])
        : "r"(a[0]), "r"(a[1]), "r"(a[2]), "r"(a[3]), "r"(b0), "r"(b1));
}
static __device__ __forceinline__ void ldsm_x4(uint32_t* r, uint32_t addr) {
    asm volatile("ldmatrix.sync.aligned.m8n8.x4.shared.b16 {%0,%1,%2,%3}, [%4];"
                 : "=r"(r[0]), "=r"(r[1]), "=r"(r[2]), "=r"(r[3]) : "r"(addr));
}
static __device__ __forceinline__ uint32_t smem_u32(const void* p) {
    uint32_t a;
    asm("{ .reg .u64 t; cvta.to.shared.u64 t, %1; cvt.u32.u64 %0, t; }" : "=r"(a) : "l"(p));
    return a;
}
static __device__ __forceinline__ void cpa16(uint32_t dst, const float* src) {
    asm volatile("cp.async.cg.shared.global [%0], [%1], 16;" :: "r"(dst), "l"(src));
}

__global__ __launch_bounds__(256, 2)
void swa_mma_kernel(const float* __restrict__ q, const float* __restrict__ k,
                    const float* __restrict__ v, float* __restrict__ out)
{
    extern __shared__ char smc[];
    const uint32_t sb = smem_u32(smc);
    uint32_t* Qh = (uint32_t*)(smc + SMB_QH);
    float*    Ks = (float*)(smc + SMB_KS);
    float*    Vs = (float*)(smc + SMB_VS);

    const int tid  = threadIdx.x;
    const int w    = tid >> 5;       // 0..7, one m16 tile each
    const int lane = tid & 31;
    const int gid  = lane >> 2;
    const int tig  = lane & 3;

    const int qt2 = (int)gridDim.x - 1 - (int)blockIdx.x;   // long CTAs first
    const int bh  = blockIdx.y;
    const int qs  = qt2 * QT;

    const float* qp = q + (size_t)bh * NQ * DH;
    const float* kp = k + (size_t)bh * NQ * DH;
    const float* vp = v + (size_t)bh * NQ * DH;

    const int kt_lo = (2 * qt2 - 8) > 0 ? (2 * qt2 - 8) : 0;
    const int kt_hi = 2 * qt2 + 1;

    // staging cell ownership (identical maps in prefetch and convert)
    const int sc  = tid & 15;        // 16B col-chunk
    const int sk0 = tid >> 4;        // base key / keypair group

    // ---- ldmatrix per-lane address components (word units) ----
    const int ls2    = (lane & 7) << 2;                                   // swizzle term
    const int qrow32 = (16 * w + (lane & 7) + 8 * ((lane >> 3) & 1)) * 32;
    const int qch    = 4 * (lane >> 4);                                   // 0 or 4 (a0/a2 half)
    const int krow32 = (8 * (lane >> 4) + (lane & 7)) * 32;               // key within 16-key grp
    const int kch    = 4 * ((lane >> 3) & 1);                             // b0/b1 half

    // ---- prefetch(kt) into staging: K swizzled chunks, V plain ----
    auto prefetch = [&](int kt) {
        const float* kg = kp + (size_t)kt * 64 * DH;
        const float* vg = vp + (size_t)kt * 64 * DH;
#pragma unroll
        for (int it = 0; it < 4; it++) {
            int key = sk0 + 16 * it;
            cpa16(sb + SMB_KS + (uint32_t)(key * 64 + 4 * (sc ^ (key & 7))) * 4,
                  kg + key * DH + 4 * sc);
        }
#pragma unroll
        for (int it = 0; it < 2; it++) {
            int b = sk0 + 16 * it;
            cpa16(sb + SMB_VS + (uint32_t)((2 * b) * 64 + 4 * sc) * 4,
                  vg + (2 * b) * DH + 4 * sc);
            cpa16(sb + SMB_VS + (uint32_t)((2 * b + 1) * 64 + 4 * sc) * 4,
                  vg + (2 * b + 1) * DH + 4 * sc);
        }
        asm volatile("cp.async.commit_group;");
    };

    // ---- convert staging -> fp16 Kh + transposed Vt (self-owned cells) ----
    auto convert = [&](uint32_t* KHd, uint32_t* VTd) {
#pragma unroll
        for (int it = 0; it < 4; it++) {
            int key = sk0 + 16 * it;
            float4 t = *(const float4*)(Ks + key * 64 + 4 * (sc ^ (key & 7)));
            uint2 wv;
            wv.x = packh2(t.x, t.y);
            wv.y = packh2(t.z, t.w);
            *(uint2*)(KHd + key * 32 + ((2 * sc) ^ ((key & 7) << 2))) = wv;
        }
#pragma unroll
        for (int it = 0; it < 2; it++) {
            int b = sk0 + 16 * it;
            float4 va = *(const float4*)(Vs + (2 * b) * 64 + 4 * sc);
            float4 vb = *(const float4*)(Vs + (2 * b + 1) * 64 + 4 * sc);
            float al[4] = {va.x, va.y, va.z, va.w};
            float bl[4] = {vb.x, vb.y, vb.z, vb.w};
#pragma unroll
            for (int e = 0; e < 4; e++) {
                int d = 4 * sc + e;
                VTd[d * 36 + (b ^ ((d >> 4) & 3))] = packh2(al[e], bl[e]);
            }
        }
    };

    // ---- prologue: prefetch t0, stage Q, convert t0, prefetch t1 ----
    prefetch(kt_lo);
#pragma unroll
    for (int i = tid; i < 2048; i += 256) {
        int row = i >> 4, c = i & 15;
        float4 t = *(const float4*)(qp + (size_t)(qs + row) * DH + 4 * c);
        uint2 wv;
        wv.x = packh2(t.x * QS2, t.y * QS2);
        wv.y = packh2(t.z * QS2, t.w * QS2);
        *(uint2*)(Qh + row * 32 + ((2 * c) ^ ((row & 7) << 2))) = wv;
    }
    asm volatile("cp.async.wait_group 0;");
    __syncthreads();
    convert((uint32_t*)(smc + SMB_KH0), (uint32_t*)(smc + SMB_VT0));
    if (kt_lo + 1 <= kt_hi) prefetch(kt_lo + 1);
    __syncthreads();

    float o[8][4];
#pragma unroll
    for (int db = 0; db < 8; db++)
#pragma unroll
        for (int j = 0; j < 4; j++) o[db][j] = 0.f;
    float mh[2] = {-1e30f, -1e30f};
    float lh[2] = {0.f, 0.f};

    int x = 0;
    for (int kt = kt_lo; kt <= kt_hi; kt++) {
        const uint32_t KHb = sb + (x ? SMB_KH1 : SMB_KH0);
        const uint32_t* VT = (const uint32_t*)(smc + (x ? SMB_VT1 : SMB_VT0));

        // ---- pipelined: convert kt+1 into idle buffer, issue prefetch kt+2 ----
        if (kt + 1 <= kt_hi) {
            asm volatile("cp.async.wait_group 0;");   // staging(kt+1) arrived
            convert((uint32_t*)(smc + (x ? SMB_KH0 : SMB_KH1)),
                    (uint32_t*)(smc + (x ? SMB_VT0 : SMB_VT1)));
            if (kt + 2 <= kt_hi) prefetch(kt + 2);    // same-thread cells: no barrier
        }

        // warp fully-masked tile skip
        const bool skip = (kt == 2 * qt2 + 1 && w < 4) || (kt == 2 * qt2 - 8 && w >= 4);
        if (!skip) {
            // ---- S = Q·K^T (fp16 m16n8k16, ldmatrix operands, batched per k-step) ----
            float s[8][4];
#pragma unroll
            for (int nb = 0; nb < 8; nb++)
#pragma unroll
                for (int j = 0; j < 4; j++) s[nb][j] = 0.f;
#pragma unroll
            for (int ks = 0; ks < 4; ks++) {
                uint32_t a0[4];
                ldsm_x4(a0, sb + SMB_QH + 4u * (uint32_t)(qrow32 + ((8 * ks + qch) ^ ls2)));
                uint32_t b[16];
#pragma unroll
                for (int g = 0; g < 4; g++)
                    ldsm_x4(b + 4 * g,
                            KHb + 4u * (uint32_t)(krow32 + g * 512 + ((8 * ks + kch) ^ ls2)));
#pragma unroll
                for (int g = 0; g < 4; g++) {
                    mma_f16(s[2 * g],     a0, b[4 * g],     b[4 * g + 1]);
                    mma_f16(s[2 * g + 1], a0, b[4 * g + 2], b[4 * g + 3]);
                }
            }

            // ---- boundary masks ----
            const bool do_mask = (kt == 2 * qt2 - 8) || (kt == 2 * qt2 - 7) ||
                                 (kt == 2 * qt2 && w < 4) || (kt == 2 * qt2 + 1);
            if (do_mask) {
#pragma unroll
                for (int nb = 0; nb < 8; nb++)
#pragma unroll
                    for (int j = 0; j < 4; j++) {
                        int cg = kt * 64 + nb * 8 + 2 * tig + (j & 1);
                        int rg = qs + 16 * w + gid + 8 * (j >> 1);
                        if (cg > rg || cg < rg - (WIN - 1)) s[nb][j] = -1e30f;
                    }
            }

            // ---- online softmax (log2 domain), 2 chains in lockstep ----
            float mx[2], corr[2], ls[2];
#pragma unroll
            for (int u = 0; u < 2; u++) {
                float m0 = fmaxf(s[0][2 * u], s[0][2 * u + 1]);
                float m1 = fmaxf(s[1][2 * u], s[1][2 * u + 1]);
                float m2 = fmaxf(s[2][2 * u], s[2][2 * u + 1]);
                float m3 = fmaxf(s[3][2 * u], s[3][2 * u + 1]);
                float m4 = fmaxf(s[4][2 * u], s[4][2 * u + 1]);
                float m5 = fmaxf(s[5][2 * u], s[5][2 * u + 1]);
                float m6 = fmaxf(s[6][2 * u], s[6][2 * u + 1]);
                float m7 = fmaxf(s[7][2 * u], s[7][2 * u + 1]);
                mx[u] = fmaxf(fmaxf(fmaxf(m0, m1), fmaxf(m2, m3)),
                              fmaxf(fmaxf(m4, m5), fmaxf(m6, m7)));
            }
#pragma unroll
            for (int u = 0; u < 2; u++) mx[u] = fmaxf(mx[u], __shfl_xor_sync(0xffffffffu, mx[u], 1));
#pragma unroll
            for (int u = 0; u < 2; u++) mx[u] = fmaxf(mx[u], __shfl_xor_sync(0xffffffffu, mx[u], 2));
#pragma unroll
            for (int u = 0; u < 2; u++) {
                float mn = fmaxf(mh[u], mx[u]);
                corr[u] = ex2f(mh[u] - mn);
                mh[u] = mn;
            }
#pragma unroll
            for (int u = 0; u < 2; u++) {
                float acc0 = 0.f, acc1 = 0.f;
#pragma unroll
                for (int nb = 0; nb < 8; nb++) {
                    float p0 = ex2f(s[nb][2 * u]     - mh[u]);
                    float p1 = ex2f(s[nb][2 * u + 1] - mh[u]);
                    s[nb][2 * u]     = p0;
                    s[nb][2 * u + 1] = p1;
                    acc0 += p0; acc1 += p1;
                }
                ls[u] = acc0 + acc1;
            }
#pragma unroll
            for (int u = 0; u < 2; u++) ls[u] += __shfl_xor_sync(0xffffffffu, ls[u], 1);
#pragma unroll
            for (int u = 0; u < 2; u++) ls[u] += __shfl_xor_sync(0xffffffffu, ls[u], 2);
#pragma unroll
            for (int u = 0; u < 2; u++) {
                lh[u] = lh[u] * corr[u] + ls[u];
#pragma unroll
                for (int db = 0; db < 8; db++) {
                    o[db][2 * u]     *= corr[u];
                    o[db][2 * u + 1] *= corr[u];
                }
            }

            // ---- O += P·V (fp16, P C-frags pack directly into A-frags) ----
#pragma unroll
            for (int j = 0; j < 4; j++) {
                uint32_t ap[4];
                ap[0] = packh2(s[2 * j][0],     s[2 * j][1]);
                ap[1] = packh2(s[2 * j][2],     s[2 * j][3]);
                ap[2] = packh2(s[2 * j + 1][0], s[2 * j + 1][1]);
                ap[3] = packh2(s[2 * j + 1][2], s[2 * j + 1][3]);
#pragma unroll
                for (int db = 0; db < 8; db++) {
                    int d = db * 8 + gid;
                    int f = (d >> 4) & 3;
                    uint32_t b0 = VT[d * 36 + ((8 * j + tig) ^ f)];
                    uint32_t b1 = VT[d * 36 + ((8 * j + tig + 4) ^ f)];
                    mma_f16(o[db], ap, b0, b1);
                }
            }
        }
        __syncthreads();    // single barrier: publishes converted buf, retires current buf
        x ^= 1;
    }

    // ---- epilogue ----
    {
        const int rl0 = 16 * w + gid;
        float inv0 = 1.0f / lh[0];
        float inv1 = 1.0f / lh[1];
        float* op = out + ((size_t)bh * NQ + qs + rl0) * DH;
#pragma unroll
        for (int db = 0; db < 8; db++) {
            *(float2*)(op + db * 8 + 2 * tig) =
                make_float2(o[db][0] * inv0, o[db][1] * inv0);
            *(float2*)(op + 8 * DH + db * 8 + 2 * tig) =
                make_float2(o[db][2] * inv1, o[db][3] * inv1);
        }
    }
}

extern "C" void kernel_launch(void* const* d_in, const int* in_sizes, int n_in,
                              void* d_out, int out_size)
{
    const float* q = (const float*)d_in[0];
    const float* k = (const float*)d_in[1];
    const float* v = (const float*)d_in[2];
    float* o = (float*)d_out;

    cudaFuncSetAttribute(swa_mma_kernel, cudaFuncAttributeMaxDynamicSharedMemorySize, SMB_TOT);
    dim3 grid(NQ / QT, 32);   // (16 query tiles, B*H)
    swa_mma_kernel<<<grid, 256, SMB_TOT>>>(q, k, v, o);
}

// round 13
// speedup vs baseline: 1.8678x; 1.1709x over previous
#include <cuda_runtime.h>
#include <cuda_fp16.h>
#include <cstdint>

#define NQ  2048
#define DH  64
#define WIN 512
#define QT  128
// 0.125 * log2(e) folded into Q; softmax in log2 domain via ex2.approx
#define QS2 0.18033688011112042f

// smem byte offsets (total 81920 B -> 2 CTAs/SM at 256 threads)
#define SMB_QH  0        // 128 rows x 32 u32 (fp16x2), word ^ ((row&7)<<2)
#define SMB_KS  16384    // K f32 staging 64x64, 16B-chunk ^ (key&7)
#define SMB_VS  32768    // V f32 staging 64x64, 16B-chunk ^ (key&7)
#define SMB_KH0 49152    // 64 keys x 32 u32 fp16x2 (same swizzle as QH)
#define SMB_KH1 57344
#define SMB_VH0 65536    // V fp16 row-major [key][d], same swizzle as KH
#define SMB_VH1 73728
#define SMB_TOT 81920

static __device__ __forceinline__ float ex2f(float x) {
    float y; asm("ex2.approx.f32 %0, %1;" : "=f"(y) : "f"(x)); return y;
}
static __device__ __forceinline__ uint32_t packh2(float lo, float hi) {
    __half2 h = __floats2half2_rn(lo, hi);
    return *(uint32_t*)&h;
}
static __device__ __forceinline__ void mma_f16(float* d, const uint32_t* a,
                                               uint32_t b0, uint32_t b1) {
    asm volatile(
        "mma.sync.aligned.m16n8k16.row.col.f32.f16.f16.f32 "
        "{%0,%1,%2,%3}, {%4,%5,%6,%7}, {%8,%9}, {%0,%1,%2,%3};"
        : "+f"(d[0]), "+f"(d[1]), "+f"(d[2]), "+f"(d[3])
        : "r"(a[0]), "r"(a[1]), "r"(a[2]), "r"(a[3]), "r"(b0), "r"(b1));
}
static __device__ __forceinline__ void ldsm_x4(uint32_t* r, uint32_t addr) {
    asm volatile("ldmatrix.sync.aligned.m8n8.x4.shared.b16 {%0,%1,%2,%3}, [%4];"
                 : "=r"(r[0]), "=r"(r[1]), "=r"(r[2]), "=r"(r[3]) : "r"(addr));
}
static __device__ __forceinline__ void ldsm_x4_t(uint32_t* r, uint32_t addr) {
    asm volatile("ldmatrix.sync.aligned.m8n8.x4.trans.shared.b16 {%0,%1,%2,%3}, [%4];"
                 : "=r"(r[0]), "=r"(r[1]), "=r"(r[2]), "=r"(r[3]) : "r"(addr));
}
static __device__ __forceinline__ uint32_t smem_u32(const void* p) {
    uint32_t a;
    asm("{ .reg .u64 t; cvta.to.shared.u64 t, %1; cvt.u32.u64 %0, t; }" : "=r"(a) : "l"(p));
    return a;
}
static __device__ __forceinline__ void cpa16(uint32_t dst, const float* src) {
    asm volatile("cp.async.cg.shared.global [%0], [%1], 16;" :: "r"(dst), "l"(src));
}

__global__ __launch_bounds__(256, 2)
void swa_mma_kernel(const float* __restrict__ q, const float* __restrict__ k,
                    const float* __restrict__ v, float* __restrict__ out)
{
    extern __shared__ char smc[];
    const uint32_t sb = smem_u32(smc);
    uint32_t* Qh = (uint32_t*)(smc + SMB_QH);
    float*    Ks = (float*)(smc + SMB_KS);
    float*    Vs = (float*)(smc + SMB_VS);

    const int tid  = threadIdx.x;
    const int w    = tid >> 5;       // 0..7, one m16 tile each
    const int lane = tid & 31;
    const int gid  = lane >> 2;
    const int tig  = lane & 3;

    const int qt2 = (int)gridDim.x - 1 - (int)blockIdx.x;   // long CTAs first
    const int bh  = blockIdx.y;
    const int qs  = qt2 * QT;

    const float* qp = q + (size_t)bh * NQ * DH;
    const float* kp = k + (size_t)bh * NQ * DH;
    const float* vp = v + (size_t)bh * NQ * DH;

    const int kt_lo = (2 * qt2 - 8) > 0 ? (2 * qt2 - 8) : 0;
    const int kt_hi = 2 * qt2 + 1;

    // staging cell ownership (identical maps in prefetch and convert)
    const int sc  = tid & 15;        // 16B col-chunk
    const int sk0 = tid >> 4;        // base key

    // ---- ldmatrix per-lane address components (word units) ----
    const int ls2    = (lane & 7) << 2;                                   // swizzle term
    const int qrow32 = (16 * w + (lane & 7) + 8 * ((lane >> 3) & 1)) * 32;
    const int qch    = 4 * (lane >> 4);                                   // a0/a2 half
    const int krow32 = (8 * (lane >> 4) + (lane & 7)) * 32;               // key within 16-key grp
    const int kch    = 4 * ((lane >> 3) & 1);                             // b0/b1 half
    // V trans ldmatrix: key = 16j + vk_off, d-chunk = 2g + (lane>>4)
    const int vk32   = (8 * ((lane >> 3) & 1) + (lane & 7)) * 32;
    const int vch    = 4 * (lane >> 4);

    // ---- prefetch(kt) into staging: K and V swizzled 16B chunks ----
    auto prefetch = [&](int kt) {
        const float* kg = kp + (size_t)kt * 64 * DH;
        const float* vg = vp + (size_t)kt * 64 * DH;
#pragma unroll
        for (int it = 0; it < 4; it++) {
            int key = sk0 + 16 * it;
            uint32_t off = (uint32_t)(key * 64 + 4 * (sc ^ (key & 7))) * 4;
            cpa16(sb + SMB_KS + off, kg + key * DH + 4 * sc);
            cpa16(sb + SMB_VS + off, vg + key * DH + 4 * sc);
        }
        asm volatile("cp.async.commit_group;");
    };

    // ---- convert staging -> fp16 Kh + fp16 row-major Vh (self-owned cells) ----
    auto convert = [&](uint32_t* KHd, uint32_t* VHd) {
#pragma unroll
        for (int it = 0; it < 4; it++) {
            int key = sk0 + 16 * it;
            float4 t = *(const float4*)(Ks + key * 64 + 4 * (sc ^ (key & 7)));
            uint2 wv;
            wv.x = packh2(t.x, t.y);
            wv.y = packh2(t.z, t.w);
            *(uint2*)(KHd + key * 32 + ((2 * sc) ^ ((key & 7) << 2))) = wv;
            float4 u = *(const float4*)(Vs + key * 64 + 4 * (sc ^ (key & 7)));
            uint2 wu;
            wu.x = packh2(u.x, u.y);
            wu.y = packh2(u.z, u.w);
            *(uint2*)(VHd + key * 32 + ((2 * sc) ^ ((key & 7) << 2))) = wu;
        }
    };

    // ---- prologue: prefetch t0, stage Q, convert t0, prefetch t1 ----
    prefetch(kt_lo);
#pragma unroll
    for (int i = tid; i < 2048; i += 256) {
        int row = i >> 4, c = i & 15;
        float4 t = *(const float4*)(qp + (size_t)(qs + row) * DH + 4 * c);
        uint2 wv;
        wv.x = packh2(t.x * QS2, t.y * QS2);
        wv.y = packh2(t.z * QS2, t.w * QS2);
        *(uint2*)(Qh + row * 32 + ((2 * c) ^ ((row & 7) << 2))) = wv;
    }
    asm volatile("cp.async.wait_group 0;");
    __syncthreads();
    convert((uint32_t*)(smc + SMB_KH0), (uint32_t*)(smc + SMB_VH0));
    if (kt_lo + 1 <= kt_hi) prefetch(kt_lo + 1);
    __syncthreads();

    float o[8][4];
#pragma unroll
    for (int db = 0; db < 8; db++)
#pragma unroll
        for (int j = 0; j < 4; j++) o[db][j] = 0.f;
    float mh[2] = {-1e30f, -1e30f};
    float lh[2] = {0.f, 0.f};

    int x = 0;
    for (int kt = kt_lo; kt <= kt_hi; kt++) {
        const uint32_t KHb = sb + (x ? SMB_KH1 : SMB_KH0);
        const uint32_t VHb = sb + (x ? SMB_VH1 : SMB_VH0);

        // ---- pipelined: convert kt+1 into idle buffer, issue prefetch kt+2 ----
        if (kt + 1 <= kt_hi) {
            asm volatile("cp.async.wait_group 0;");   // staging(kt+1) arrived
            convert((uint32_t*)(smc + (x ? SMB_KH0 : SMB_KH1)),
                    (uint32_t*)(smc + (x ? SMB_VH0 : SMB_VH1)));
            if (kt + 2 <= kt_hi) prefetch(kt + 2);    // same-thread cells: no barrier
        }

        // warp fully-masked tile skip
        const bool skip = (kt == 2 * qt2 + 1 && w < 4) || (kt == 2 * qt2 - 8 && w >= 4);
        if (!skip) {
            // ---- S = Q·K^T (fp16 m16n8k16, ldmatrix operands) ----
            float s[8][4];
#pragma unroll
            for (int nb = 0; nb < 8; nb++)
#pragma unroll
                for (int j = 0; j < 4; j++) s[nb][j] = 0.f;
#pragma unroll
            for (int ks = 0; ks < 4; ks++) {
                uint32_t a0[4];
                ldsm_x4(a0, sb + SMB_QH + 4u * (uint32_t)(qrow32 + ((8 * ks + qch) ^ ls2)));
                uint32_t b[16];
#pragma unroll
                for (int g = 0; g < 4; g++)
                    ldsm_x4(b + 4 * g,
                            KHb + 4u * (uint32_t)(krow32 + g * 512 + ((8 * ks + kch) ^ ls2)));
#pragma unroll
                for (int g = 0; g < 4; g++) {
                    mma_f16(s[2 * g],     a0, b[4 * g],     b[4 * g + 1]);
                    mma_f16(s[2 * g + 1], a0, b[4 * g + 2], b[4 * g + 3]);
                }
            }

            // ---- boundary masks ----
            const bool do_mask = (kt == 2 * qt2 - 8) || (kt == 2 * qt2 - 7) ||
                                 (kt == 2 * qt2 && w < 4) || (kt == 2 * qt2 + 1);
            if (do_mask) {
#pragma unroll
                for (int nb = 0; nb < 8; nb++)
#pragma unroll
                    for (int j = 0; j < 4; j++) {
                        int cg = kt * 64 + nb * 8 + 2 * tig + (j & 1);
                        int rg = qs + 16 * w + gid + 8 * (j >> 1);
                        if (cg > rg || cg < rg - (WIN - 1)) s[nb][j] = -1e30f;
                    }
            }

            // ---- online softmax (log2 domain), 2 chains in lockstep ----
            float mx[2], corr[2], ls[2];
#pragma unroll
            for (int u = 0; u < 2; u++) {
                float m0 = fmaxf(s[0][2 * u], s[0][2 * u + 1]);
                float m1 = fmaxf(s[1][2 * u], s[1][2 * u + 1]);
                float m2 = fmaxf(s[2][2 * u], s[2][2 * u + 1]);
                float m3 = fmaxf(s[3][2 * u], s[3][2 * u + 1]);
                float m4 = fmaxf(s[4][2 * u], s[4][2 * u + 1]);
                float m5 = fmaxf(s[5][2 * u], s[5][2 * u + 1]);
                float m6 = fmaxf(s[6][2 * u], s[6][2 * u + 1]);
                float m7 = fmaxf(s[7][2 * u], s[7][2 * u + 1]);
                mx[u] = fmaxf(fmaxf(fmaxf(m0, m1), fmaxf(m2, m3)),
                              fmaxf(fmaxf(m4, m5), fmaxf(m6, m7)));
            }
#pragma unroll
            for (int u = 0; u < 2; u++) mx[u] = fmaxf(mx[u], __shfl_xor_sync(0xffffffffu, mx[u], 1));
#pragma unroll
            for (int u = 0; u < 2; u++) mx[u] = fmaxf(mx[u], __shfl_xor_sync(0xffffffffu, mx[u], 2));
#pragma unroll
            for (int u = 0; u < 2; u++) {
                float mn = fmaxf(mh[u], mx[u]);
                corr[u] = ex2f(mh[u] - mn);
                mh[u] = mn;
            }
#pragma unroll
            for (int u = 0; u < 2; u++) {
                float acc0 = 0.f, acc1 = 0.f;
#pragma unroll
                for (int nb = 0; nb < 8; nb++) {
                    float p0 = ex2f(s[nb][2 * u]     - mh[u]);
                    float p1 = ex2f(s[nb][2 * u + 1] - mh[u]);
                    s[nb][2 * u]     = p0;
                    s[nb][2 * u + 1] = p1;
                    acc0 += p0; acc1 += p1;
                }
                ls[u] = acc0 + acc1;
            }
#pragma unroll
            for (int u = 0; u < 2; u++) ls[u] += __shfl_xor_sync(0xffffffffu, ls[u], 1);
#pragma unroll
            for (int u = 0; u < 2; u++) ls[u] += __shfl_xor_sync(0xffffffffu, ls[u], 2);
#pragma unroll
            for (int u = 0; u < 2; u++) {
                lh[u] = lh[u] * corr[u] + ls[u];
#pragma unroll
                for (int db = 0; db < 8; db++) {
                    o[db][2 * u]     *= corr[u];
                    o[db][2 * u + 1] *= corr[u];
                }
            }

            // ---- O += P·V : fp16, V fragments via ldmatrix.trans on row-major Vh ----
#pragma unroll
            for (int j = 0; j < 4; j++) {
                uint32_t ap[4];
                ap[0] = packh2(s[2 * j][0],     s[2 * j][1]);
                ap[1] = packh2(s[2 * j][2],     s[2 * j][3]);
                ap[2] = packh2(s[2 * j + 1][0], s[2 * j + 1][1]);
                ap[3] = packh2(s[2 * j + 1][2], s[2 * j + 1][3]);
#pragma unroll
                for (int g = 0; g < 4; g++) {
                    uint32_t rv[4];
                    ldsm_x4_t(rv, VHb + 4u * (uint32_t)(j * 512 + vk32 + ((8 * g + vch) ^ ls2)));
                    mma_f16(o[2 * g],     ap, rv[0], rv[1]);
                    mma_f16(o[2 * g + 1], ap, rv[2], rv[3]);
                }
            }
        }
        __syncthreads();    // single barrier: publishes converted buf, retires current buf
        x ^= 1;
    }

    // ---- epilogue ----
    {
        const int rl0 = 16 * w + gid;
        float inv0 = 1.0f / lh[0];
        float inv1 = 1.0f / lh[1];
        float* op = out + ((size_t)bh * NQ + qs + rl0) * DH;
#pragma unroll
        for (int db = 0; db < 8; db++) {
            *(float2*)(op + db * 8 + 2 * tig) =
                make_float2(o[db][0] * inv0, o[db][1] * inv0);
            *(float2*)(op + 8 * DH + db * 8 + 2 * tig) =
                make_float2(o[db][2] * inv1, o[db][3] * inv1);
        }
    }
}

extern "C" void kernel_launch(void* const* d_in, const int* in_sizes, int n_in,
                              void* d_out, int out_size)
{
    const float* q = (const float*)d_in[0];
    const float* k = (const float*)d_in[1];
    const float* v = (const float*)d_in[2];
    float* o = (float*)d_out;

    cudaFuncSetAttribute(swa_mma_kernel, cudaFuncAttributeMaxDynamicSharedMemorySize, SMB_TOT);
    dim3 grid(NQ / QT, 32);   // (16 query tiles, B*H)
    swa_mma_kernel<<<grid, 256, SMB_TOT>>>(q, k, v, o);
}

// round 14
// speedup vs baseline: 1.9469x; 1.0423x over previous
#include <cuda_runtime.h>
#include <cuda_fp16.h>
#include <cstdint>

#define NQ  2048
#define DH  64
#define WIN 512
#define QT  128
// 0.125 * log2(e) folded into Q; softmax in log2 domain via ex2.approx
#define QS2 0.18033688011112042f
#define HONES 0x3C003C00u   // fp16x2 {1.0, 1.0}

// smem byte offsets (total 81920 B -> 2 CTAs/SM at 256 threads)
#define SMB_QH  0        // 128 rows x 32 u32 (fp16x2), word ^ ((row&7)<<2)
#define SMB_KS  16384    // K f32 staging 64x64, 16B-chunk ^ (key&7)
#define SMB_VS  32768    // V f32 staging 64x64, 16B-chunk ^ (key&7)
#define SMB_KH0 49152    // 64 keys x 32 u32 fp16x2 (same swizzle as QH)
#define SMB_KH1 57344
#define SMB_VH0 65536    // V fp16 row-major [key][d], same swizzle as KH
#define SMB_VH1 73728
#define SMB_TOT 81920

static __device__ __forceinline__ float ex2f(float x) {
    float y; asm("ex2.approx.f32 %0, %1;" : "=f"(y) : "f"(x)); return y;
}
static __device__ __forceinline__ uint32_t packh2(float lo, float hi) {
    __half2 h = __floats2half2_rn(lo, hi);
    return *(uint32_t*)&h;
}
// exp2 of a float pair, computed in packed fp16 (result is an fp16x2 A-frag word)
static __device__ __forceinline__ uint32_t h2exp2(float a, float b) {
    uint32_t p = packh2(a, b);
    uint32_t r; asm("ex2.approx.f16x2 %0, %1;" : "=r"(r) : "r"(p));
    return r;
}
static __device__ __forceinline__ void mma_f16(float* d, const uint32_t* a,
                                               uint32_t b0, uint32_t b1) {
    asm volatile(
        "mma.sync.aligned.m16n8k16.row.col.f32.f16.f16.f32 "
        "{%0,%1,%2,%3}, {%4,%5,%6,%7}, {%8,%9}, {%0,%1,%2,%3};"
        : "+f"(d[0]), "+f"(d[1]), "+f"(d[2]), "+f"(d[3])
        : "r"(a[0]), "r"(a[1]), "r"(a[2]), "r"(a[3]), "r"(b0), "r"(b1));
}
static __device__ __forceinline__ void ldsm_x4(uint32_t* r, uint32_t addr) {
    asm volatile("ldmatrix.sync.aligned.m8n8.x4.shared.b16 {%0,%1,%2,%3}, [%4];"
                 : "=r"(r[0]), "=r"(r[1]), "=r"(r[2]), "=r"(r[3]) : "r"(addr));
}
static __device__ __forceinline__ void ldsm_x4_t(uint32_t* r, uint32_t addr) {
    asm volatile("ldmatrix.sync.aligned.m8n8.x4.trans.shared.b16 {%0,%1,%2,%3}, [%4];"
                 : "=r"(r[0]), "=r"(r[1]), "=r"(r[2]), "=r"(r[3]) : "r"(addr));
}
static __device__ __forceinline__ uint32_t smem_u32(const void* p) {
    uint32_t a;
    asm("{ .reg .u64 t; cvta.to.shared.u64 t, %1; cvt.u32.u64 %0, t; }" : "=r"(a) : "l"(p));
    return a;
}
static __device__ __forceinline__ void cpa16(uint32_t dst, const float* src) {
    asm volatile("cp.async.cg.shared.global [%0], [%1], 16;" :: "r"(dst), "l"(src));
}

__global__ __launch_bounds__(256, 2)
void swa_mma_kernel(const float* __restrict__ q, const float* __restrict__ k,
                    const float* __restrict__ v, float* __restrict__ out)
{
    extern __shared__ char smc[];
    const uint32_t sb = smem_u32(smc);
    uint32_t* Qh = (uint32_t*)(smc + SMB_QH);
    float*    Ks = (float*)(smc + SMB_KS);
    float*    Vs = (float*)(smc + SMB_VS);

    const int tid  = threadIdx.x;
    const int w    = tid >> 5;       // 0..7, one m16 tile each
    const int lane = tid & 31;
    const int gid  = lane >> 2;
    const int tig  = lane & 3;

    const int qt2 = (int)gridDim.x - 1 - (int)blockIdx.x;   // long CTAs first
    const int bh  = blockIdx.y;
    const int qs  = qt2 * QT;

    const float* qp = q + (size_t)bh * NQ * DH;
    const float* kp = k + (size_t)bh * NQ * DH;
    const float* vp = v + (size_t)bh * NQ * DH;

    const int kt_lo = (2 * qt2 - 8) > 0 ? (2 * qt2 - 8) : 0;
    const int kt_hi = 2 * qt2 + 1;

    // staging cell ownership (identical maps in prefetch and convert)
    const int sc  = tid & 15;        // 16B col-chunk
    const int sk0 = tid >> 4;        // base key

    // ---- ldmatrix per-lane address components (word units) ----
    const int ls2    = (lane & 7) << 2;                                   // swizzle term
    const int qrow32 = (16 * w + (lane & 7) + 8 * ((lane >> 3) & 1)) * 32;
    const int qch    = 4 * (lane >> 4);                                   // a0/a2 half
    const int krow32 = (8 * (lane >> 4) + (lane & 7)) * 32;               // key within 16-key grp
    const int kch    = 4 * ((lane >> 3) & 1);                             // b0/b1 half
    const int vk32   = (8 * ((lane >> 3) & 1) + (lane & 7)) * 32;
    const int vch    = 4 * (lane >> 4);

    // ---- prefetch(kt) into staging: K and V swizzled 16B chunks ----
    auto prefetch = [&](int kt) {
        const float* kg = kp + (size_t)kt * 64 * DH;
        const float* vg = vp + (size_t)kt * 64 * DH;
#pragma unroll
        for (int it = 0; it < 4; it++) {
            int key = sk0 + 16 * it;
            uint32_t off = (uint32_t)(key * 64 + 4 * (sc ^ (key & 7))) * 4;
            cpa16(sb + SMB_KS + off, kg + key * DH + 4 * sc);
            cpa16(sb + SMB_VS + off, vg + key * DH + 4 * sc);
        }
        asm volatile("cp.async.commit_group;");
    };

    // ---- convert staging -> fp16 Kh + fp16 row-major Vh (self-owned cells) ----
    auto convert = [&](uint32_t* KHd, uint32_t* VHd) {
#pragma unroll
        for (int it = 0; it < 4; it++) {
            int key = sk0 + 16 * it;
            float4 t = *(const float4*)(Ks + key * 64 + 4 * (sc ^ (key & 7)));
            uint2 wv;
            wv.x = packh2(t.x, t.y);
            wv.y = packh2(t.z, t.w);
            *(uint2*)(KHd + key * 32 + ((2 * sc) ^ ((key & 7) << 2))) = wv;
            float4 u = *(const float4*)(Vs + key * 64 + 4 * (sc ^ (key & 7)));
            uint2 wu;
            wu.x = packh2(u.x, u.y);
            wu.y = packh2(u.z, u.w);
            *(uint2*)(VHd + key * 32 + ((2 * sc) ^ ((key & 7) << 2))) = wu;
        }
    };

    // ---- prologue: prefetch t0, stage Q, convert t0, prefetch t1 ----
    prefetch(kt_lo);
#pragma unroll
    for (int i = tid; i < 2048; i += 256) {
        int row = i >> 4, c = i & 15;
        float4 t = *(const float4*)(qp + (size_t)(qs + row) * DH + 4 * c);
        uint2 wv;
        wv.x = packh2(t.x * QS2, t.y * QS2);
        wv.y = packh2(t.z * QS2, t.w * QS2);
        *(uint2*)(Qh + row * 32 + ((2 * c) ^ ((row & 7) << 2))) = wv;
    }
    asm volatile("cp.async.wait_group 0;");
    __syncthreads();
    convert((uint32_t*)(smc + SMB_KH0), (uint32_t*)(smc + SMB_VH0));
    if (kt_lo + 1 <= kt_hi) prefetch(kt_lo + 1);
    __syncthreads();

    float o[8][4];
#pragma unroll
    for (int db = 0; db < 8; db++)
#pragma unroll
        for (int j = 0; j < 4; j++) o[db][j] = 0.f;
    float mh[2] = {-1e30f, -1e30f};
    float lh[2] = {0.f, 0.f};

    int x = 0;
    for (int kt = kt_lo; kt <= kt_hi; kt++) {
        const uint32_t KHb = sb + (x ? SMB_KH1 : SMB_KH0);
        const uint32_t VHb = sb + (x ? SMB_VH1 : SMB_VH0);

        // ---- pipelined: convert kt+1 into idle buffer, issue prefetch kt+2 ----
        if (kt + 1 <= kt_hi) {
            asm volatile("cp.async.wait_group 0;");   // staging(kt+1) arrived
            convert((uint32_t*)(smc + (x ? SMB_KH0 : SMB_KH1)),
                    (uint32_t*)(smc + (x ? SMB_VH0 : SMB_VH1)));
            if (kt + 2 <= kt_hi) prefetch(kt + 2);    // same-thread cells: no barrier
        }

        // warp fully-masked tile skip
        const bool skip = (kt == 2 * qt2 + 1 && w < 4) || (kt == 2 * qt2 - 8 && w >= 4);
        if (!skip) {
            // ---- S = Q·K^T (fp16 m16n8k16, ldmatrix operands) ----
            float s[8][4];
#pragma unroll
            for (int nb = 0; nb < 8; nb++)
#pragma unroll
                for (int j = 0; j < 4; j++) s[nb][j] = 0.f;
#pragma unroll
            for (int ks = 0; ks < 4; ks++) {
                uint32_t a0[4];
                ldsm_x4(a0, sb + SMB_QH + 4u * (uint32_t)(qrow32 + ((8 * ks + qch) ^ ls2)));
                uint32_t b[16];
#pragma unroll
                for (int g = 0; g < 4; g++)
                    ldsm_x4(b + 4 * g,
                            KHb + 4u * (uint32_t)(krow32 + g * 512 + ((8 * ks + kch) ^ ls2)));
#pragma unroll
                for (int g = 0; g < 4; g++) {
                    mma_f16(s[2 * g],     a0, b[4 * g],     b[4 * g + 1]);
                    mma_f16(s[2 * g + 1], a0, b[4 * g + 2], b[4 * g + 3]);
                }
            }

            // ---- boundary masks ----
            const bool do_mask = (kt == 2 * qt2 - 8) || (kt == 2 * qt2 - 7) ||
                                 (kt == 2 * qt2 && w < 4) || (kt == 2 * qt2 + 1);
            if (do_mask) {
#pragma unroll
                for (int nb = 0; nb < 8; nb++)
#pragma unroll
                    for (int j = 0; j < 4; j++) {
                        int cg = kt * 64 + nb * 8 + 2 * tig + (j & 1);
                        int rg = qs + 16 * w + gid + 8 * (j >> 1);
                        if (cg > rg || cg < rg - (WIN - 1)) s[nb][j] = -1e30f;
                    }
            }

            // ---- online softmax: f32 max trees, fp16x2 exp, l via ones-mma ----
            float mx[2], corr[2];
#pragma unroll
            for (int u = 0; u < 2; u++) {
                float m0 = fmaxf(s[0][2 * u], s[0][2 * u + 1]);
                float m1 = fmaxf(s[1][2 * u], s[1][2 * u + 1]);
                float m2 = fmaxf(s[2][2 * u], s[2][2 * u + 1]);
                float m3 = fmaxf(s[3][2 * u], s[3][2 * u + 1]);
                float m4 = fmaxf(s[4][2 * u], s[4][2 * u + 1]);
                float m5 = fmaxf(s[5][2 * u], s[5][2 * u + 1]);
                float m6 = fmaxf(s[6][2 * u], s[6][2 * u + 1]);
                float m7 = fmaxf(s[7][2 * u], s[7][2 * u + 1]);
                mx[u] = fmaxf(fmaxf(fmaxf(m0, m1), fmaxf(m2, m3)),
                              fmaxf(fmaxf(m4, m5), fmaxf(m6, m7)));
            }
#pragma unroll
            for (int u = 0; u < 2; u++) mx[u] = fmaxf(mx[u], __shfl_xor_sync(0xffffffffu, mx[u], 1));
#pragma unroll
            for (int u = 0; u < 2; u++) mx[u] = fmaxf(mx[u], __shfl_xor_sync(0xffffffffu, mx[u], 2));
#pragma unroll
            for (int u = 0; u < 2; u++) {
                float mn = fmaxf(mh[u], mx[u]);
                corr[u] = ex2f(mh[u] - mn);
                mh[u] = mn;
            }
            // rescale O
#pragma unroll
            for (int u = 0; u < 2; u++)
#pragma unroll
                for (int db = 0; db < 8; db++) {
                    o[db][2 * u]     *= corr[u];
                    o[db][2 * u + 1] *= corr[u];
                }
            // P fragments: exp in packed fp16 (directly the A-frag words)
            uint32_t ap[4][4];
#pragma unroll
            for (int j = 0; j < 4; j++) {
                ap[j][0] = h2exp2(s[2 * j][0]     - mh[0], s[2 * j][1]     - mh[0]);
                ap[j][1] = h2exp2(s[2 * j][2]     - mh[1], s[2 * j][3]     - mh[1]);
                ap[j][2] = h2exp2(s[2 * j + 1][0] - mh[0], s[2 * j + 1][1] - mh[0]);
                ap[j][3] = h2exp2(s[2 * j + 1][2] - mh[1], s[2 * j + 1][3] - mh[1]);
            }

            // ---- O += P·V  and  l += P·1 (ones-B mma; exact f32 sum of fp16 P) ----
            float lsum[4] = {0.f, 0.f, 0.f, 0.f};
#pragma unroll
            for (int j = 0; j < 4; j++) {
#pragma unroll
                for (int g = 0; g < 4; g++) {
                    uint32_t rv[4];
                    ldsm_x4_t(rv, VHb + 4u * (uint32_t)(j * 512 + vk32 + ((8 * g + vch) ^ ls2)));
                    mma_f16(o[2 * g],     ap[j], rv[0], rv[1]);
                    mma_f16(o[2 * g + 1], ap[j], rv[2], rv[3]);
                }
                mma_f16(lsum, ap[j], HONES, HONES);
            }
            lh[0] = lh[0] * corr[0] + lsum[0];
            lh[1] = lh[1] * corr[1] + lsum[2];
        }
        __syncthreads();    // single barrier: publishes converted buf, retires current buf
        x ^= 1;
    }

    // ---- epilogue ----
    {
        const int rl0 = 16 * w + gid;
        float inv0 = 1.0f / lh[0];
        float inv1 = 1.0f / lh[1];
        float* op = out + ((size_t)bh * NQ + qs + rl0) * DH;
#pragma unroll
        for (int db = 0; db < 8; db++) {
            *(float2*)(op + db * 8 + 2 * tig) =
                make_float2(o[db][0] * inv0, o[db][1] * inv0);
            *(float2*)(op + 8 * DH + db * 8 + 2 * tig) =
                make_float2(o[db][2] * inv1, o[db][3] * inv1);
        }
    }
}

extern "C" void kernel_launch(void* const* d_in, const int* in_sizes, int n_in,
                              void* d_out, int out_size)
{
    const float* q = (const float*)d_in[0];
    const float* k = (const float*)d_in[1];
    const float* v = (const float*)d_in[2];
    float* o = (float*)d_out;

    cudaFuncSetAttribute(swa_mma_kernel, cudaFuncAttributeMaxDynamicSharedMemorySize, SMB_TOT);
    dim3 grid(NQ / QT, 32);   // (16 query tiles, B*H)
    swa_mma_kernel<<<grid, 256, SMB_TOT>>>(q, k, v, o);
}